// round 1
// baseline (speedup 1.0000x reference)
#include <cuda_runtime.h>
#include <cstdint>

// Problem constants (shapes fixed by the dataset problem)
#define ROWS 64            // B*N
#define PP   147456        // H*W
#define KCLS 3
#define NBIN 4096
#define CHUNKS 16
#define CHUNK  (PP / CHUNKS)          // 9216
#define THREADS 256
#define ITERS   (CHUNK / (THREADS*4)) // 9
#define FXD 1073741824.0              // 2^30 fixed-point scale

// -------- scratch (no allocations allowed; device globals) --------
__device__ float g_nll [(size_t)ROWS * PP];
__device__ float g_side[(size_t)ROWS * PP];
__device__ unsigned int g_hist[ROWS * NBIN];
__device__ unsigned int g_sidecnt[ROWS];
__device__ int g_bstar[ROWS];
__device__ int g_needed[ROWS];
__device__ int g_m;
__device__ unsigned long long g_total;

__device__ __forceinline__ unsigned int nbits(float v) {
    // nll values are >= 0; canonicalize -0 / tiny negatives to bits 0
    return (v > 0.0f) ? __float_as_uint(v) : 0u;
}

__device__ __forceinline__ float nllsel(int t, float a, float b, float c) {
    if (t == 255) return 0.0f;                 // ignore_index
    float v = (t == 0) ? a : (t == 1) ? b : c;
    return -v;
}

// -------- K0: zero scratch, decode step_percent -> m --------
__global__ void k0_init(const void* sp_ptr, int has_sp) {
    int i = blockIdx.x * blockDim.x + threadIdx.x;
    for (; i < ROWS * NBIN; i += gridDim.x * blockDim.x) g_hist[i] = 0u;
    if (blockIdx.x == 0) {
        if (threadIdx.x < ROWS) g_sidecnt[threadIdx.x] = 0u;
        if (threadIdx.x == 0) {
            g_total = 0ull;
            double sp = 1.0;
            if (has_sp) {
                unsigned int bits = *(const unsigned int*)sp_ptr;
                if (bits < 1024u) sp = (double)(int)bits;      // int32 scalar
                else              sp = (double)__uint_as_float(bits); // float32 scalar
            }
            if (sp > 1.0) sp = 1.0;
            if (sp < 0.0) sp = 0.0;
            double md = sp * 0.15 * (double)PP + (1.0 - sp) * (double)PP;
            int m = (int)md;
            if (m < 1) m = 1;
            if (m > PP) m = PP;
            g_m = m;
        }
    }
}

// -------- K1: nll compute + buffer + per-row 4096-bin histogram --------
__global__ void __launch_bounds__(THREADS) k1_nll(const float* __restrict__ inp,
                                                  const int*   __restrict__ tgt) {
    __shared__ unsigned int sh[NBIN];
    for (int i = threadIdx.x; i < NBIN; i += THREADS) sh[i] = 0u;
    __syncthreads();

    int row = blockIdx.x / CHUNKS;
    int seg = blockIdx.x % CHUNKS;
    size_t tbase = (size_t)row * PP + (size_t)seg * CHUNK;
    const float* p0 = inp + (size_t)row * KCLS * PP + (size_t)seg * CHUNK;
    const float* p1 = p0 + PP;
    const float* p2 = p0 + 2 * PP;
    const int*   tg = tgt + tbase;
    float*       ob = g_nll + tbase;

#pragma unroll
    for (int it = 0; it < ITERS; ++it) {
        int off = it * (THREADS * 4) + threadIdx.x * 4;
        int4   t4 = *(const int4*)(tg + off);
        float4 a  = *(const float4*)(p0 + off);
        float4 b  = *(const float4*)(p1 + off);
        float4 c  = *(const float4*)(p2 + off);
        float4 o;
        o.x = nllsel(t4.x, a.x, b.x, c.x);
        o.y = nllsel(t4.y, a.y, b.y, c.y);
        o.z = nllsel(t4.z, a.z, b.z, c.z);
        o.w = nllsel(t4.w, a.w, b.w, c.w);
        atomicAdd(&sh[min(nbits(o.x) >> 19, (unsigned)(NBIN - 1))], 1u);
        atomicAdd(&sh[min(nbits(o.y) >> 19, (unsigned)(NBIN - 1))], 1u);
        atomicAdd(&sh[min(nbits(o.z) >> 19, (unsigned)(NBIN - 1))], 1u);
        atomicAdd(&sh[min(nbits(o.w) >> 19, (unsigned)(NBIN - 1))], 1u);
        *(float4*)(ob + off) = o;
    }
    __syncthreads();
    for (int i = threadIdx.x; i < NBIN; i += THREADS) {
        unsigned int v = sh[i];
        if (v) atomicAdd(&g_hist[row * NBIN + i], v);
    }
}

// -------- K2: per-row threshold bin via suffix scan --------
__global__ void __launch_bounds__(THREADS) k2_thresh() {
    int row = blockIdx.x;
    __shared__ unsigned int sh[NBIN];
    __shared__ unsigned int cs[THREADS];
    for (int i = threadIdx.x; i < NBIN; i += THREADS) sh[i] = g_hist[row * NBIN + i];
    __syncthreads();
    unsigned s = 0;
    int base = threadIdx.x * (NBIN / THREADS); // 16 bins each
    for (int j = 0; j < NBIN / THREADS; ++j) s += sh[base + j];
    cs[threadIdx.x] = s;
    __syncthreads();
    if (threadIdx.x == 0) {
        unsigned m = (unsigned)g_m;
        unsigned acc = 0, above = 0;
        int bstar = 0;
        for (int j = THREADS - 1; j >= 0; --j) {
            if (acc + cs[j] >= m) {
                for (int b = j * 16 + 15; b >= j * 16; --b) {
                    acc += sh[b];
                    if (acc >= m) { bstar = b; above = acc - sh[b]; break; }
                }
                break;
            }
            acc += cs[j];
        }
        g_bstar[row]  = bstar;
        g_needed[row] = (int)m - (int)above;
    }
}

// -------- K3: sum strictly-above bins; compact threshold-bin values --------
__device__ __forceinline__ void k3_elem(float v, int bstar, double& s,
                                        float* sb, int row) {
    unsigned bits = nbits(v);
    int bin = (int)(bits >> 19);
    if (bin > bstar) s += (double)v;
    bool q = (bin == bstar);
    unsigned bal = __ballot_sync(0xffffffffu, q);
    if (q) {
        int lane = threadIdx.x & 31;
        int leader = __ffs(bal) - 1;
        unsigned base;
        if (lane == leader) base = atomicAdd(&g_sidecnt[row], (unsigned)__popc(bal));
        base = __shfl_sync(bal, base, leader);
        sb[base + __popc(bal & ((1u << lane) - 1u))] = v;
    }
}

__global__ void __launch_bounds__(THREADS) k3_sum() {
    int row = blockIdx.x / CHUNKS;
    int seg = blockIdx.x % CHUNKS;
    int bstar = g_bstar[row];
    size_t tbase = (size_t)row * PP + (size_t)seg * CHUNK;
    const float* ib = g_nll + tbase;
    float* sb = g_side + (size_t)row * PP;
    double s = 0.0;
#pragma unroll
    for (int it = 0; it < ITERS; ++it) {
        int off = it * (THREADS * 4) + threadIdx.x * 4;
        float4 v = *(const float4*)(ib + off);
        k3_elem(v.x, bstar, s, sb, row);
        k3_elem(v.y, bstar, s, sb, row);
        k3_elem(v.z, bstar, s, sb, row);
        k3_elem(v.w, bstar, s, sb, row);
    }
    __shared__ double red[THREADS];
    red[threadIdx.x] = s;
    __syncthreads();
    for (int st = THREADS / 2; st > 0; st >>= 1) {
        if (threadIdx.x < st) red[threadIdx.x] += red[threadIdx.x + st];
        __syncthreads();
    }
    if (threadIdx.x == 0 && red[0] > 0.0)
        atomicAdd(&g_total, (unsigned long long)(red[0] * FXD + 0.5));
}

// -------- K4: exact select inside the threshold bin (2 radix levels) --------
__global__ void __launch_bounds__(THREADS) k4_side() {
    int row = blockIdx.x;
    int needed = g_needed[row];
    if (needed <= 0) return;
    int cnt = (int)g_sidecnt[row];
    const float* sb = g_side + (size_t)row * PP;
    int tid = threadIdx.x;

    __shared__ unsigned int h[NBIN];
    __shared__ unsigned int cs[THREADS];
    __shared__ double red[THREADS];
    __shared__ unsigned int hb[128];
    __shared__ int s_b2, s_need2, s_b3, s_need3;

    for (int i = tid; i < NBIN; i += THREADS) h[i] = 0u;
    __syncthreads();
    for (int i = tid; i < cnt; i += THREADS) {
        unsigned bits = nbits(sb[i]);
        atomicAdd(&h[(bits >> 7) & 0xFFFu], 1u);
    }
    __syncthreads();
    unsigned s = 0;
    int base = tid * (NBIN / THREADS);
    for (int j = 0; j < NBIN / THREADS; ++j) s += h[base + j];
    cs[tid] = s;
    __syncthreads();
    if (tid == 0) {
        unsigned acc = 0, above = 0; int b2 = 0;
        for (int j = THREADS - 1; j >= 0; --j) {
            if (acc + cs[j] >= (unsigned)needed) {
                for (int b = j * 16 + 15; b >= j * 16; --b) {
                    acc += h[b];
                    if (acc >= (unsigned)needed) { b2 = b; above = acc - h[b]; break; }
                }
                break;
            }
            acc += cs[j];
        }
        s_b2 = b2; s_need2 = needed - (int)above;
    }
    for (int i = tid; i < 128; i += THREADS) hb[i] = 0u;
    __syncthreads();
    int b2 = s_b2, need2 = s_need2;

    double sum1 = 0.0;
    for (int i = tid; i < cnt; i += THREADS) {
        float v = sb[i];
        unsigned bits = nbits(v);
        int b = (int)((bits >> 7) & 0xFFFu);
        if (b > b2) sum1 += (double)v;
        else if (b == b2) atomicAdd(&hb[bits & 0x7Fu], 1u);
    }
    red[tid] = sum1;
    __syncthreads();
    for (int st = THREADS / 2; st > 0; st >>= 1) {
        if (tid < st) red[tid] += red[tid + st];
        __syncthreads();
    }
    double sum_gt2 = red[0];                 // read by all before next write-barrier
    if (tid == 0) {
        unsigned acc = 0, above = 0; int b3 = 0;
        for (int b = 127; b >= 0; --b) {
            acc += hb[b];
            if (acc >= (unsigned)need2) { b3 = b; above = acc - hb[b]; break; }
        }
        s_b3 = b3; s_need3 = need2 - (int)above;
    }
    __syncthreads();
    int b3 = s_b3, need3 = s_need3;

    double sum2 = 0.0;
    for (int i = tid; i < cnt; i += THREADS) {
        float v = sb[i];
        unsigned bits = nbits(v);
        if ((int)((bits >> 7) & 0xFFFu) == b2 && (int)(bits & 0x7Fu) > b3)
            sum2 += (double)v;
    }
    red[tid] = sum2;
    __syncthreads();
    for (int st = THREADS / 2; st > 0; st >>= 1) {
        if (tid < st) red[tid] += red[tid + st];
        __syncthreads();
    }
    if (tid == 0) {
        unsigned tb = ((unsigned)g_bstar[row] << 19) | ((unsigned)b2 << 7) | (unsigned)b3;
        float tv = __uint_as_float(tb);
        double contrib = sum_gt2 + red[0] + (double)need3 * (double)tv;
        if (contrib > 0.0)
            atomicAdd(&g_total, (unsigned long long)(contrib * FXD + 0.5));
    }
}

// -------- K5: finalize mean --------
__global__ void k5_final(float* out) {
    if (threadIdx.x == 0 && blockIdx.x == 0) {
        double tot = (double)g_total / FXD;
        out[0] = (float)(tot / ((double)ROWS * (double)g_m));
    }
}

extern "C" void kernel_launch(void* const* d_in, const int* in_sizes, int n_in,
                              void* d_out, int out_size) {
    const float* inp = (const float*)d_in[0];
    const int*   tgt = (const int*)d_in[1];
    const void*  sp  = (n_in > 2) ? d_in[2] : nullptr;
    (void)in_sizes; (void)out_size;

    k0_init<<<256, THREADS>>>(sp, (n_in > 2) ? 1 : 0);
    k1_nll<<<ROWS * CHUNKS, THREADS>>>(inp, tgt);
    k2_thresh<<<ROWS, THREADS>>>();
    k3_sum<<<ROWS * CHUNKS, THREADS>>>();
    k4_side<<<ROWS, THREADS>>>();
    k5_final<<<1, 32>>>((float*)d_out);
}